// round 13
// baseline (speedup 1.0000x reference)
#include <cuda_runtime.h>
#include <cstdint>

#define BB 64
#define NN 576
#define DD 768
#define KK 1024
#define NT 2
#define ROWS (BB * NN)          // 36864
#define NPAIR (BB * KK)         // 65536
#define OUT_MAIN (NPAIR * NT)   // 131072
#define NV4 (DD / 4)            // 192 float4 per row
#define GRID 592                // 4 blocks/SM x 148 SMs: one co-resident wave

// Per-row projections P[b*N+n] = {z.W0[:,0], z.W0[:,1], z.W1[:,0], z.W1[:,1]}.
__device__ float4 g_P[ROWS];
// Grid barrier counter (generation-counted, monotonic, graph-replay-safe).
__device__ unsigned int g_bar;

// Fused: projection (32 warps/SM, L2-prefetched) -> grid barrier -> gather.
__global__ __launch_bounds__(256, 4) void partvit_fused_kernel(
    const float* __restrict__ z, const int* __restrict__ idx,
    const float* __restrict__ W, const float* __restrict__ bh,
    float* __restrict__ out, int out_size) {
    int tid  = threadIdx.x;
    int lane = tid & 31;
    int gtid = blockIdx.x * 256 + tid;

    // ---- Weights: conflict-free component-major smem table (12 KB) ----
    __shared__ float4 Wc[4][NV4];
    // Prefetched idx pair parked in smem (saves registers across phase 1).
    __shared__ int2 s_pr[256];
    for (int f = tid; f < DD; f += 256) {
        int c = f / NV4, i4 = f - c * NV4;
        int d = 4 * i4 + c;
        Wc[c][i4] = make_float4(W[2 * d], W[2 * d + 1],
                                W[2 * (d + DD)], W[2 * (d + DD) + 1]);
    }
    s_pr[tid] = (gtid < NPAIR) ? reinterpret_cast<const int2*>(idx)[gtid]
                               : make_int2(0, 0);
    __syncthreads();

    // ---- Phase 1: projection, static grid-stride (4 rows per warp-iter) ----
    int gw = gtid >> 5;
    int nw = (GRID * 256) >> 5;   // 4736 warps over 9216 warp-iters (~2 each)

    for (int it = gw; it < ROWS / 4; it += nw) {
        int row = it * 4;
        const float4* z4 = reinterpret_cast<const float4*>(z + (size_t)row * DD);

        // L2 prefetch: this iter's 12 KB (helps j=1..5) and next iter's 12 KB
        // (each warp runs ~2 iters). 3 instrs x (32 lanes x 128B) = 12 KB each.
        {
            const char* self = (const char*)z4;
            int itn = it + nw;
            int rown = (itn < ROWS / 4) ? itn * 4 : row;
            const char* nxt = (const char*)(z + (size_t)rown * DD);
            #pragma unroll
            for (int q = 0; q < 3; q++) {
                asm volatile("prefetch.global.L2 [%0];"
                             :: "l"(self + q * 4096 + lane * 128));
                asm volatile("prefetch.global.L2 [%0];"
                             :: "l"(nxt + q * 4096 + lane * 128));
            }
        }

        float4 a0 = {0,0,0,0}, a1 = {0,0,0,0}, a2 = {0,0,0,0}, a3 = {0,0,0,0};
        #pragma unroll 1
        for (int j = 0; j < 6; j++) {
            int i4 = lane + 32 * j;
            float4 z0 = z4[0 * NV4 + i4];
            float4 z1 = z4[1 * NV4 + i4];
            float4 z2 = z4[2 * NV4 + i4];
            float4 z3 = z4[3 * NV4 + i4];
            float4 w0 = Wc[0][i4];
            float4 w1 = Wc[1][i4];
            float4 w2 = Wc[2][i4];
            float4 w3 = Wc[3][i4];
            a0.x += z0.x*w0.x + z0.y*w1.x + z0.z*w2.x + z0.w*w3.x;
            a0.y += z0.x*w0.y + z0.y*w1.y + z0.z*w2.y + z0.w*w3.y;
            a0.z += z0.x*w0.z + z0.y*w1.z + z0.z*w2.z + z0.w*w3.z;
            a0.w += z0.x*w0.w + z0.y*w1.w + z0.z*w2.w + z0.w*w3.w;
            a1.x += z1.x*w0.x + z1.y*w1.x + z1.z*w2.x + z1.w*w3.x;
            a1.y += z1.x*w0.y + z1.y*w1.y + z1.z*w2.y + z1.w*w3.y;
            a1.z += z1.x*w0.z + z1.y*w1.z + z1.z*w2.z + z1.w*w3.z;
            a1.w += z1.x*w0.w + z1.y*w1.w + z1.z*w2.w + z1.w*w3.w;
            a2.x += z2.x*w0.x + z2.y*w1.x + z2.z*w2.x + z2.w*w3.x;
            a2.y += z2.x*w0.y + z2.y*w1.y + z2.z*w2.y + z2.w*w3.y;
            a2.z += z2.x*w0.z + z2.y*w1.z + z2.z*w2.z + z2.w*w3.z;
            a2.w += z2.x*w0.w + z2.y*w1.w + z2.z*w2.w + z2.w*w3.w;
            a3.x += z3.x*w0.x + z3.y*w1.x + z3.z*w2.x + z3.w*w3.x;
            a3.y += z3.x*w0.y + z3.y*w1.y + z3.z*w2.y + z3.w*w3.y;
            a3.z += z3.x*w0.z + z3.y*w1.z + z3.z*w2.z + z3.w*w3.z;
            a3.w += z3.x*w0.w + z3.y*w1.w + z3.z*w2.w + z3.w*w3.w;
        }

        #pragma unroll
        for (int off = 16; off; off >>= 1) {
            a0.x += __shfl_xor_sync(0xffffffffu, a0.x, off);
            a0.y += __shfl_xor_sync(0xffffffffu, a0.y, off);
            a0.z += __shfl_xor_sync(0xffffffffu, a0.z, off);
            a0.w += __shfl_xor_sync(0xffffffffu, a0.w, off);
            a1.x += __shfl_xor_sync(0xffffffffu, a1.x, off);
            a1.y += __shfl_xor_sync(0xffffffffu, a1.y, off);
            a1.z += __shfl_xor_sync(0xffffffffu, a1.z, off);
            a1.w += __shfl_xor_sync(0xffffffffu, a1.w, off);
            a2.x += __shfl_xor_sync(0xffffffffu, a2.x, off);
            a2.y += __shfl_xor_sync(0xffffffffu, a2.y, off);
            a2.z += __shfl_xor_sync(0xffffffffu, a2.z, off);
            a2.w += __shfl_xor_sync(0xffffffffu, a2.w, off);
            a3.x += __shfl_xor_sync(0xffffffffu, a3.x, off);
            a3.y += __shfl_xor_sync(0xffffffffu, a3.y, off);
            a3.z += __shfl_xor_sync(0xffffffffu, a3.z, off);
            a3.w += __shfl_xor_sync(0xffffffffu, a3.w, off);
        }
        if (lane == 0) {
            g_P[row + 0] = a0;
            g_P[row + 1] = a1;
            g_P[row + 2] = a2;
            g_P[row + 3] = a3;
        }
    }

    // ---- Device-wide barrier (generation-counted, replay-safe) ----
    __syncthreads();
    if (tid == 0) {
        __threadfence();                               // release g_P writes
        unsigned old = atomicAdd(&g_bar, 1u);
        unsigned target = (old / GRID) * GRID + GRID;  // this generation's goal
        unsigned v;
        do {
            asm volatile("ld.global.acquire.gpu.u32 %0, [%1];"
                         : "=r"(v) : "l"(&g_bar));
            if ((int)(v - target) >= 0) break;
            __nanosleep(64);
        } while (true);
    }
    __syncthreads();

    // ---- Phase 2: gather (pair gtid) ----
    if (gtid >= NPAIR) return;
    int2 pr = s_pr[tid];
    float bh0 = bh[0], bh1 = bh[1];                    // L2-hot reload
    int b  = gtid >> 10;                               // gtid / KK
    int i0 = min(max(pr.x, 0), NN - 1);
    int i1 = min(max(pr.y, 0), NN - 1);

    float4 p0 = g_P[b * NN + i0];   // pair elem 0 -> W[0:D] halves (.x,.y)
    float4 p1 = g_P[b * NN + i1];   // pair elem 1 -> W[D:2D] halves (.z,.w)

    float2 o;
    o.x = p0.x + p1.z + bh0;
    o.y = p0.y + p1.w + bh1;
    reinterpret_cast<float2*>(out)[gtid] = o;

    // If the harness flattens the (out, indices) tuple, echo indices as f32.
    if (out_size >= OUT_MAIN + 2 * NPAIR) {
        out[OUT_MAIN + 2 * gtid + 0] = (float)pr.x;
        out[OUT_MAIN + 2 * gtid + 1] = (float)pr.y;
    }
}

extern "C" void kernel_launch(void* const* d_in, const int* in_sizes, int n_in,
                              void* d_out, int out_size) {
    const float* z   = (const float*)d_in[0];      // [B, N, D] f32
    const int*   idx = (const int*)d_in[1];        // [B, K, 2] i32
    const float* W   = (const float*)d_in[2];      // [2D, NT] f32
    const float* bh  = (const float*)d_in[3];      // [NT] f32
    float* out = (float*)d_out;

    partvit_fused_kernel<<<GRID, 256>>>(z, idx, W, bh, out, out_size);
}

// round 14
// speedup vs baseline: 1.1628x; 1.1628x over previous
#include <cuda_runtime.h>
#include <cstdint>

#define BB 64
#define NN 576
#define DD 768
#define KK 1024
#define NT 2
#define ROWS (BB * NN)          // 36864
#define NPAIR (BB * KK)         // 65536
#define OUT_MAIN (NPAIR * NT)   // 131072
#define NC8 (DD / 8)            // 96 float8 chunks per row
#define GRID 740                // 5 blocks/SM x 148 SMs: one co-resident wave

// Per-row projections P[b*N+n] = {z.W0[:,0], z.W0[:,1], z.W1[:,0], z.W1[:,1]}.
__device__ float4 g_P[ROWS];
// Grid barrier counter (generation-counted, monotonic, graph-replay-safe).
__device__ unsigned int g_bar;

// 256-bit global load (8 x f32), sm_100+ PTX form.
__device__ __forceinline__ void ldg256(float* v, const float* p) {
    uint32_t u0, u1, u2, u3, u4, u5, u6, u7;
    asm volatile("ld.global.nc.v8.b32 {%0,%1,%2,%3,%4,%5,%6,%7}, [%8];"
                 : "=r"(u0), "=r"(u1), "=r"(u2), "=r"(u3),
                   "=r"(u4), "=r"(u5), "=r"(u6), "=r"(u7)
                 : "l"(p));
    v[0] = __uint_as_float(u0); v[1] = __uint_as_float(u1);
    v[2] = __uint_as_float(u2); v[3] = __uint_as_float(u3);
    v[4] = __uint_as_float(u4); v[5] = __uint_as_float(u5);
    v[6] = __uint_as_float(u6); v[7] = __uint_as_float(u7);
}

// Fused: projection (LDG.256, 40 warps/SM) -> grid barrier -> gather.
__global__ __launch_bounds__(256, 5) void partvit_fused_kernel(
    const float* __restrict__ z, const int* __restrict__ idx,
    const float* __restrict__ W, const float* __restrict__ bh,
    float* __restrict__ out, int out_size) {
    int tid  = threadIdx.x;
    int lane = tid & 31;
    int gtid = blockIdx.x * 256 + tid;

    // Wg[k][l8] = {W[d][0], W[d][1], W[d+D][0], W[d+D][1]} for d = 8*l8 + k.
    // Lane stride in l8 = 16B -> conflict-free LDS.128. 12 KB.
    __shared__ float4 Wg[8][NC8];
    __shared__ int2 s_pr[256];      // prefetched idx pairs (reg relief)
    for (int d = tid; d < DD; d += 256) {
        int k = d & 7, l8 = d >> 3;
        Wg[k][l8] = make_float4(W[2 * d], W[2 * d + 1],
                                W[2 * (d + DD)], W[2 * (d + DD) + 1]);
    }
    s_pr[tid] = (gtid < NPAIR) ? reinterpret_cast<const int2*>(idx)[gtid]
                               : make_int2(0, 0);
    __syncthreads();

    // ---- Phase 1: projection, 2 rows per warp-iter, float8 loads ----
    int gw = gtid >> 5;
    int nw = (GRID * 256) >> 5;     // 5920 warps over 18432 warp-iters (~3.1 ea)

    for (int it = gw; it < ROWS / 2; it += nw) {
        int row = it * 2;
        const float* zr0 = z + (size_t)row * DD;
        const float* zr1 = zr0 + DD;

        // v[i]: i=0..3 -> row0 comps {00,01,10,11}; i=4..7 -> row1 comps.
        float v[8] = {0, 0, 0, 0, 0, 0, 0, 0};
        #pragma unroll 1
        for (int j = 0; j < 3; j++) {
            int l8 = lane + 32 * j;
            float z0[8], z1[8];
            ldg256(z0, zr0 + l8 * 8);
            ldg256(z1, zr1 + l8 * 8);
            #pragma unroll
            for (int k = 0; k < 8; k++) {
                float4 wk = Wg[k][l8];
                v[0] += z0[k] * wk.x;
                v[1] += z0[k] * wk.y;
                v[2] += z0[k] * wk.z;
                v[3] += z0[k] * wk.w;
                v[4] += z1[k] * wk.x;
                v[5] += z1[k] * wk.y;
                v[6] += z1[k] * wk.z;
                v[7] += z1[k] * wk.w;
            }
        }

        // Value-splitting butterfly: 8 values -> 1 per lane in 9 shfl + 9 add.
        // After split steps, lane l holds value idx = 4*b0(l) + 2*b1(l) + b2(l).
        {
            bool b;
            b = (lane & 1);
            #pragma unroll
            for (int i = 0; i < 4; i++) {
                float send = b ? v[i] : v[i + 4];
                float keep = b ? v[i + 4] : v[i];
                v[i] = keep + __shfl_xor_sync(0xffffffffu, send, 1);
            }
            b = (lane & 2);
            #pragma unroll
            for (int i = 0; i < 2; i++) {
                float send = b ? v[i] : v[i + 2];
                float keep = b ? v[i + 2] : v[i];
                v[i] = keep + __shfl_xor_sync(0xffffffffu, send, 2);
            }
            b = (lane & 4);
            {
                float send = b ? v[0] : v[1];
                float keep = b ? v[1] : v[0];
                v[0] = keep + __shfl_xor_sync(0xffffffffu, send, 4);
            }
            v[0] += __shfl_xor_sync(0xffffffffu, v[0], 8);
            v[0] += __shfl_xor_sync(0xffffffffu, v[0], 16);
        }
        if (lane < 8) {
            int vi = ((lane & 1) << 2) | (lane & 2) | ((lane & 4) >> 2);
            reinterpret_cast<float*>(&g_P[row])[vi] = v[0];
        }
    }

    // ---- Device-wide barrier (generation-counted, replay-safe) ----
    __syncthreads();
    if (tid == 0) {
        __threadfence();                               // release g_P writes
        unsigned old = atomicAdd(&g_bar, 1u);
        unsigned target = (old / GRID) * GRID + GRID;  // this generation's goal
        unsigned v;
        do {
            asm volatile("ld.global.acquire.gpu.u32 %0, [%1];"
                         : "=r"(v) : "l"(&g_bar));
            if ((int)(v - target) >= 0) break;
            __nanosleep(64);
        } while (true);
    }
    __syncthreads();

    // ---- Phase 2: gather (pair gtid) ----
    if (gtid >= NPAIR) return;
    int2 pr = s_pr[tid];
    float bh0 = bh[0], bh1 = bh[1];                    // L2-hot reload
    int b  = gtid >> 10;                               // gtid / KK
    int i0 = min(max(pr.x, 0), NN - 1);
    int i1 = min(max(pr.y, 0), NN - 1);

    float4 p0 = g_P[b * NN + i0];   // pair elem 0 -> W[0:D] halves (.x,.y)
    float4 p1 = g_P[b * NN + i1];   // pair elem 1 -> W[D:2D] halves (.z,.w)

    float2 o;
    o.x = p0.x + p1.z + bh0;
    o.y = p0.y + p1.w + bh1;
    reinterpret_cast<float2*>(out)[gtid] = o;

    // If the harness flattens the (out, indices) tuple, echo indices as f32.
    if (out_size >= OUT_MAIN + 2 * NPAIR) {
        out[OUT_MAIN + 2 * gtid + 0] = (float)pr.x;
        out[OUT_MAIN + 2 * gtid + 1] = (float)pr.y;
    }
}

extern "C" void kernel_launch(void* const* d_in, const int* in_sizes, int n_in,
                              void* d_out, int out_size) {
    const float* z   = (const float*)d_in[0];      // [B, N, D] f32
    const int*   idx = (const int*)d_in[1];        // [B, K, 2] i32
    const float* W   = (const float*)d_in[2];      // [2D, NT] f32
    const float* bh  = (const float*)d_in[3];      // [NT] f32
    float* out = (float*)d_out;

    partvit_fused_kernel<<<GRID, 256>>>(z, idx, W, bh, out, out_size);
}

// round 15
// speedup vs baseline: 1.3146x; 1.1305x over previous
#include <cuda_runtime.h>
#include <cstdint>

#define BB 64
#define NN 576
#define DD 768
#define KK 1024
#define NT 2
#define ROWS (BB * NN)          // 36864
#define NPAIR (BB * KK)         // 65536
#define OUT_MAIN (NPAIR * NT)   // 131072
#define NV4 (DD / 4)            // 192 float4 per row
#define BPB 9                   // blocks per batch
#define GRID (BB * BPB)         // 576 <= 592 co-residency capacity @ 4 blocks/SM
#define WPB (BPB * 8)           // 72 warps per batch; 144 warp-iters -> 2 each

// Per-row projections P[b*N+n] = {z.W0[:,0], z.W0[:,1], z.W1[:,0], z.W1[:,1]}.
__device__ float4 g_P[ROWS];
// Per-batch arrival counters (generation-counted, monotonic, replay-safe).
__device__ unsigned int g_done[BB];

// Fused per-batch pipeline: 9 blocks project one batch's 576 rows, sync on the
// batch counter, then gather that batch's 1024 pairs. Batches overlap.
__global__ __launch_bounds__(256, 4) void partvit_fused_kernel(
    const float* __restrict__ z, const int* __restrict__ idx,
    const float* __restrict__ W, const float* __restrict__ bh,
    float* __restrict__ out, int out_size) {
    int tid  = threadIdx.x;
    int lane = tid & 31;
    int b    = blockIdx.x / BPB;        // batch
    int r    = blockIdx.x % BPB;        // block-in-batch (0..8)

    // ---- Weights: conflict-free component-major smem table (12 KB) ----
    __shared__ float4 Wc[4][NV4];
    __shared__ int2 s_pr[256];          // this block's gather pairs (r < 4)
    for (int f = tid; f < DD; f += 256) {
        int c = f / NV4, i4 = f - c * NV4;
        int d = 4 * i4 + c;
        Wc[c][i4] = make_float4(W[2 * d], W[2 * d + 1],
                                W[2 * (d + DD)], W[2 * (d + DD) + 1]);
    }
    // Prefetch this block's idx pairs (blocks 0..3 of each batch gather 256 each).
    int gpair = b * KK + r * 256 + tid;   // valid when r < 4
    s_pr[tid] = (r < 4) ? reinterpret_cast<const int2*>(idx)[gpair]
                        : make_int2(0, 0);
    __syncthreads();

    // ---- Phase 1: project this batch's rows (R12 inner loop, unchanged) ----
    int wb = r * 8 + (tid >> 5);        // warp-in-batch: 0..71
    #pragma unroll 1
    for (int s = 0; s < 2; s++) {
        int it  = wb + WPB * s;         // 0..143
        int row = b * NN + it * 4;
        const float4* z4 = reinterpret_cast<const float4*>(z + (size_t)row * DD);

        float4 a0 = {0,0,0,0}, a1 = {0,0,0,0}, a2 = {0,0,0,0}, a3 = {0,0,0,0};
        #pragma unroll 1
        for (int j = 0; j < 6; j++) {
            int i4 = lane + 32 * j;
            float4 z0 = z4[0 * NV4 + i4];
            float4 z1 = z4[1 * NV4 + i4];
            float4 z2 = z4[2 * NV4 + i4];
            float4 z3 = z4[3 * NV4 + i4];
            float4 w0 = Wc[0][i4];
            float4 w1 = Wc[1][i4];
            float4 w2 = Wc[2][i4];
            float4 w3 = Wc[3][i4];
            a0.x += z0.x*w0.x + z0.y*w1.x + z0.z*w2.x + z0.w*w3.x;
            a0.y += z0.x*w0.y + z0.y*w1.y + z0.z*w2.y + z0.w*w3.y;
            a0.z += z0.x*w0.z + z0.y*w1.z + z0.z*w2.z + z0.w*w3.z;
            a0.w += z0.x*w0.w + z0.y*w1.w + z0.z*w2.w + z0.w*w3.w;
            a1.x += z1.x*w0.x + z1.y*w1.x + z1.z*w2.x + z1.w*w3.x;
            a1.y += z1.x*w0.y + z1.y*w1.y + z1.z*w2.y + z1.w*w3.y;
            a1.z += z1.x*w0.z + z1.y*w1.z + z1.z*w2.z + z1.w*w3.z;
            a1.w += z1.x*w0.w + z1.y*w1.w + z1.z*w2.w + z1.w*w3.w;
            a2.x += z2.x*w0.x + z2.y*w1.x + z2.z*w2.x + z2.w*w3.x;
            a2.y += z2.x*w0.y + z2.y*w1.y + z2.z*w2.y + z2.w*w3.y;
            a2.z += z2.x*w0.z + z2.y*w1.z + z2.z*w2.z + z2.w*w3.z;
            a2.w += z2.x*w0.w + z2.y*w1.w + z2.z*w2.w + z2.w*w3.w;
            a3.x += z3.x*w0.x + z3.y*w1.x + z3.z*w2.x + z3.w*w3.x;
            a3.y += z3.x*w0.y + z3.y*w1.y + z3.z*w2.y + z3.w*w3.y;
            a3.z += z3.x*w0.z + z3.y*w1.z + z3.z*w2.z + z3.w*w3.z;
            a3.w += z3.x*w0.w + z3.y*w1.w + z3.z*w2.w + z3.w*w3.w;
        }

        #pragma unroll
        for (int off = 16; off; off >>= 1) {
            a0.x += __shfl_xor_sync(0xffffffffu, a0.x, off);
            a0.y += __shfl_xor_sync(0xffffffffu, a0.y, off);
            a0.z += __shfl_xor_sync(0xffffffffu, a0.z, off);
            a0.w += __shfl_xor_sync(0xffffffffu, a0.w, off);
            a1.x += __shfl_xor_sync(0xffffffffu, a1.x, off);
            a1.y += __shfl_xor_sync(0xffffffffu, a1.y, off);
            a1.z += __shfl_xor_sync(0xffffffffu, a1.z, off);
            a1.w += __shfl_xor_sync(0xffffffffu, a1.w, off);
            a2.x += __shfl_xor_sync(0xffffffffu, a2.x, off);
            a2.y += __shfl_xor_sync(0xffffffffu, a2.y, off);
            a2.z += __shfl_xor_sync(0xffffffffu, a2.z, off);
            a2.w += __shfl_xor_sync(0xffffffffu, a2.w, off);
            a3.x += __shfl_xor_sync(0xffffffffu, a3.x, off);
            a3.y += __shfl_xor_sync(0xffffffffu, a3.y, off);
            a3.z += __shfl_xor_sync(0xffffffffu, a3.z, off);
            a3.w += __shfl_xor_sync(0xffffffffu, a3.w, off);
        }
        if (lane == 0) {
            g_P[row + 0] = a0;
            g_P[row + 1] = a1;
            g_P[row + 2] = a2;
            g_P[row + 3] = a3;
        }
    }

    // ---- Per-batch barrier (generation-counted, replay-safe) ----
    __syncthreads();
    if (tid == 0) {
        __threadfence();                                  // release g_P writes
        unsigned old = atomicAdd(&g_done[b], 1u);
        unsigned target = (old / BPB) * BPB + BPB;        // this generation
        unsigned v;
        do {
            asm volatile("ld.global.acquire.gpu.u32 %0, [%1];"
                         : "=r"(v) : "l"(&g_done[b]));
            if ((int)(v - target) >= 0) break;
            __nanosleep(32);
        } while (true);
    }
    __syncthreads();

    // ---- Phase 2: gather this batch's pairs (blocks 0..3, 256 pairs each) ----
    if (r >= 4) return;
    int2 pr = s_pr[tid];
    float bh0 = bh[0], bh1 = bh[1];                       // L2-hot
    int i0 = min(max(pr.x, 0), NN - 1);
    int i1 = min(max(pr.y, 0), NN - 1);

    float4 p0 = g_P[b * NN + i0];   // pair elem 0 -> W[0:D] halves (.x,.y)
    float4 p1 = g_P[b * NN + i1];   // pair elem 1 -> W[D:2D] halves (.z,.w)

    float2 o;
    o.x = p0.x + p1.z + bh0;
    o.y = p0.y + p1.w + bh1;
    reinterpret_cast<float2*>(out)[gpair] = o;

    // If the harness flattens the (out, indices) tuple, echo indices as f32.
    if (out_size >= OUT_MAIN + 2 * NPAIR) {
        out[OUT_MAIN + 2 * gpair + 0] = (float)pr.x;
        out[OUT_MAIN + 2 * gpair + 1] = (float)pr.y;
    }
}

extern "C" void kernel_launch(void* const* d_in, const int* in_sizes, int n_in,
                              void* d_out, int out_size) {
    const float* z   = (const float*)d_in[0];      // [B, N, D] f32
    const int*   idx = (const int*)d_in[1];        // [B, K, 2] i32
    const float* W   = (const float*)d_in[2];      // [2D, NT] f32
    const float* bh  = (const float*)d_in[3];      // [NT] f32
    float* out = (float*)d_out;

    partvit_fused_kernel<<<GRID, 256>>>(z, idx, W, bh, out, out_size);
}